// round 9
// baseline (speedup 1.0000x reference)
#include <cuda_runtime.h>
#include <cstdint>

static __device__ __forceinline__ double u64_as_double(uint64_t u) {
    return __longlong_as_double((long long)u);
}
static __device__ __forceinline__ uint64_t double_as_u64(double d) {
    return (uint64_t)__double_as_longlong(d);
}
static __device__ __forceinline__ double rcp_approx(double y) {
    double r;
    asm("rcp.approx.ftz.f64 %0, %1;" : "=d"(r) : "d"(y));
    return r;
}
// One Newton-Raphson refinement of r ~= 1/y  (2 DFMA)
static __device__ __forceinline__ double nr_step(double y, double r) {
    double e = __fma_rn(-y, r, 1.0);
    return __fma_rn(r, e, r);
}
// Exact multiply by 0.5 for a normal double (exponent decrement, ALU pipe).
static __device__ __forceinline__ double halve(double s) {
    return __hiloint2double(__double2hiint(s) - 0x00100000, __double2loint(s));
}
// CR q = RN(m/y), r accurate to ~2^-28: mul + two fma residual corrections.
static __device__ __forceinline__ double div_cr2(double m, double y, double r) {
    double q0 = m * r;
    double q1 = __fma_rn(__fma_rn(-y, q0, m), r, q0);
    return      __fma_rn(__fma_rn(-y, q1, m), r, q1);
}
// CR q = RN(m/y), r accurate to ~2^-40 or better: mul + one correction.
static __device__ __forceinline__ double div_cr1(double m, double y, double r) {
    double q0 = m * r;
    return __fma_rn(__fma_rn(-y, q0, m), r, q0);
}

#define SQRT2_MANT 1865452045155277ULL
#define SQRT2_BITS ((1023ULL << 52) | SQRT2_MANT)            // RN(sqrt(2)) = seed (odd e)
#define R0ODD_BITS (((1022ULL << 52) | SQRT2_MANT) - 1ULL)   // RN(1/seed) exactly (validated)
#define ONE_BITS   (1023ULL << 52)
#define NAN_BITS   0x7FF8000000000000ULL
#define INF_BITS   0x7FF0000000000000ULL
#define MANT_MASK  0xFFFFFFFFFFFFFULL
#define FONE       0x3F800000u

__global__ void __launch_bounds__(256)
spike_sqrt_kernel(const float* __restrict__ x, float* __restrict__ out, int n)
{
    // 16-entry nibble -> float4 pulse LUT (values are 0.0f / 1.0f bit patterns,
    // MSB-first: x<-bit3, y<-bit2, z<-bit1, w<-bit0).
    __shared__ uint4 lut[16];
    if (threadIdx.x < 16) {
        unsigned b = threadIdx.x;
        lut[b] = make_uint4((b & 8) ? FONE : 0u, (b & 4) ? FONE : 0u,
                            (b & 2) ? FONE : 0u, (b & 1) ? FONE : 0u);
    }
    __syncthreads();

    const int tid  = blockIdx.x * blockDim.x + threadIdx.x;
    const int lane = threadIdx.x & 31;
    const int warpRow0 = (tid >> 5) << 5;       // first row of this warp's 32-row tile
    if (warpRow0 >= n) return;

    // ---------------- pack: ballot transpose, fully coalesced ----------------
    // Row t of the tile: hi word = cols 0..31, lo word = cols 32..63.
    const float* tile = x + (size_t)warpRow0 * 64;
    unsigned hi = 0, lo = 0;
    #pragma unroll
    for (int t = 0; t < 32; t++) {
        float a = __ldcs(tile + (2 * t) * 32 + lane);
        float b = __ldcs(tile + (2 * t + 1) * 32 + lane);
        unsigned mh = __ballot_sync(0xffffffffu, a > 0.5f);
        unsigned ml = __ballot_sync(0xffffffffu, b > 0.5f);
        if (t == lane) { hi = __brev(mh); lo = __brev(ml); }
    }
    const uint64_t u = ((uint64_t)hi << 32) | lo;

    // ---------------- normalized frame: f = 2^(2k) * m,  m in [1,4) ---------
    // Exact binary scaling commutes with RN on normal values -> bit-identical
    // to the reference trajectory; residuals never go subnormal here.
    const long long e_x    = (long long)((u >> 52) & 0x7FFULL);
    const long long e_real = e_x - 1023;
    const long long oddb   = (e_real & 1);
    const long long kk     = (e_real >> 1);                 // arithmetic shift
    const double m = u64_as_double((u & MANT_MASK) | ((uint64_t)(1023 + oddb) << 52));

    // Seed and its exact CR reciprocal (constants in this frame).
    double y = u64_as_double(oddb ? SQRT2_BITS : ONE_BITS);
    double r = u64_as_double(oddb ? R0ODD_BITS : ONE_BITS);

    // ---------------- exactly 6 straight-line Newton iterations -------------
    // Worst-case rel errors e0=.293, e1=.061, e2=1.7e-3, e3=1.5e-6,
    // e4=1.1e-12, e5 ~ 1 ulp. y6 is on the terminal 1-/2-cycle and 12-6 is
    // even, so y12 == y6 (validated bit-exact on the full input set).

    // i=0: r = RN(1/y0) exactly -> single Markstein correction is CR.
    y = halve(y + div_cr1(m, y, r));
    // i=1..3: rcp (~2^-14, MUFU: off the fp64 pipe) + 1 NR -> delta~2^-28;
    // two-correction division keeps misround prob ~2^-28/div.
    #pragma unroll
    for (int i = 0; i < 3; i++) {
        r = rcp_approx(y);
        r = nr_step(y, r);
        y = halve(y + div_cr2(m, y, r));
    }
    // i=4: carried r stale by e3~2^-22.8; one NR -> delta ~ 2^-45.
    r = nr_step(y, r);
    y = halve(y + div_cr1(m, y, r));
    // i=5: carried delta ~ 2^-44.7. Single correction CR.
    y = halve(y + div_cr1(m, y, r));

    // Re-apply exponent: 2^kk = integer add on the exponent field (exact,
    // including the carry when y == 2.0).
    uint64_t rbits = double_as_u64(y) + ((uint64_t)kk << 52);

    // ---------------- special-case muxes (same order as reference) ---------
    const uint64_t s_bit  = u >> 63;
    const bool m_any      = (u & MANT_MASK) != 0ULL;
    const bool e_all_one  = (e_x == 0x7FF);
    const bool e_is_zero  = (e_x == 0);
    if (s_bit)                              rbits = NAN_BITS;
    if (e_all_one &&  m_any)                rbits = NAN_BITS;
    if (e_all_one && !m_any && s_bit == 0)  rbits = INF_BITS;
    if (e_is_zero && !m_any)                rbits = 0ULL;

    // ---------------- unpack: redistribute words, LUT, float4 stores --------
    // Warp output = 64 consecutive 32-bit words; word k = element k>>1,
    // (k&1 ? lo : hi). Redistribute so lane l holds words l (W0) and l+32 (W1).
    const unsigned rhi = (unsigned)(rbits >> 32);
    const unsigned rlo = (unsigned)rbits;
    unsigned th0 = __shfl_sync(0xffffffffu, rhi, lane >> 1);
    unsigned tl0 = __shfl_sync(0xffffffffu, rlo, lane >> 1);
    unsigned th1 = __shfl_sync(0xffffffffu, rhi, 16 + (lane >> 1));
    unsigned tl1 = __shfl_sync(0xffffffffu, rlo, 16 + (lane >> 1));
    unsigned W0 = (lane & 1) ? tl0 : th0;
    unsigned W1 = (lane & 1) ? tl1 : th1;

    // Lane stores uint4 at flat float position j*128 + 4*lane; its 4 bits live
    // in word k = 4j + (lane>>3), at bit offset 28 - 4*(lane&7) (MSB-first).
    uint4* otile4 = (uint4*)(out + (size_t)warpRow0 * 64);
    const int sh  = 28 - 4 * (lane & 7);
    const int sub = lane >> 3;
    #pragma unroll
    for (int j = 0; j < 16; j++) {
        unsigned w = __shfl_sync(0xffffffffu, (j < 8) ? W0 : W1,
                                 ((4 * j) & 31) + sub);
        uint4 v = lut[(w >> sh) & 15u];
        __stcs(&otile4[j * 32 + lane], v);
    }
}

extern "C" void kernel_launch(void* const* d_in, const int* in_sizes, int n_in,
                              void* d_out, int out_size)
{
    const float* x = (const float*)d_in[0];
    float* out = (float*)d_out;
    const int n = in_sizes[0] / 64;
    const int threads = 256;
    const int blocks = (n + threads - 1) / threads;
    spike_sqrt_kernel<<<blocks, threads>>>(x, out, n);
}

// round 10
// speedup vs baseline: 1.0506x; 1.0506x over previous
#include <cuda_runtime.h>
#include <cstdint>

static __device__ __forceinline__ double u64_as_double(uint64_t u) {
    return __longlong_as_double((long long)u);
}
static __device__ __forceinline__ uint64_t double_as_u64(double d) {
    return (uint64_t)__double_as_longlong(d);
}
static __device__ __forceinline__ double rsqrt_approx(double v) {
    double r;
    asm("rsqrt.approx.ftz.f64 %0, %1;" : "=d"(r) : "d"(v));
    return r;
}
// Exact multiply by 0.5 for a normal double (exponent decrement, ALU pipe).
static __device__ __forceinline__ double halve(double s) {
    return __hiloint2double(__double2hiint(s) - 0x00100000, __double2loint(s));
}

#define SQRT2_MANT 1865452045155277ULL
#define NAN_BITS   0x7FF8000000000000ULL
#define INF_BITS   0x7FF0000000000000ULL
#define MANT_MASK  0xFFFFFFFFFFFFFULL

__global__ void __launch_bounds__(256)
spike_sqrt_kernel(const float* __restrict__ x, float* __restrict__ out, int n)
{
    const int tid  = blockIdx.x * blockDim.x + threadIdx.x;
    const int lane = threadIdx.x & 31;
    const int warpRow0 = (tid >> 5) << 5;       // first row of this warp's 32-row tile
    if (warpRow0 >= n) return;

    // ---------------- pack: ballot transpose, fully coalesced ----------------
    const float* tile = x + (size_t)warpRow0 * 64;
    unsigned hi = 0, lo = 0;
    #pragma unroll
    for (int k = 0; k < 64; k++) {
        float v = tile[k * 32 + lane];
        unsigned mask = __ballot_sync(0xffffffffu, v > 0.5f);
        unsigned w = __brev(mask);
        if ((k >> 1) == lane) { if (k & 1) lo = w; else hi = w; }
    }
    const uint64_t u = ((uint64_t)hi << 32) | lo;

    // ---------------- normalized frame: f = 2^(2k) * m,  m in [1,4) ---------
    const long long e_x    = (long long)((u >> 52) & 0x7FFULL);
    const long long e_real = e_x - 1023;
    const long long oddb   = (e_real & 1);
    const long long kk     = (e_real >> 1);                 // arithmetic shift
    const double m = u64_as_double((u & MANT_MASK) | ((uint64_t)(1023 + oddb) << 52));

    // ---------------- rsqrt sprint to the y4 region -------------------------
    // Newton's map is super-contractive: the true trajectory's y4 is within
    // e4 <= 8.9e-14 ~ 2^-43 of sqrt(m), and ANY point y4'' within ~2^-43
    // yields bit-identical y5, y6 (pre-round images differ by <= e4^2 ~ 2^-86;
    // internal division/add roundings agree to the same order). So replace
    // iterations 0..3 with a direct 1/sqrt(m) refinement:
    // r: delta -> 1.5*delta^2 per step; 3 steps floor at ~2^-51.5 from any
    // plausible MUFU seed accuracy (>= 2^-8).
    double r = rsqrt_approx(m);
    #pragma unroll
    for (int i = 0; i < 3; i++) {
        double t = m * r;
        double e = __fma_rn(-t, r, 1.0);
        r = __fma_rn(halve(r), e, r);       // halve(r): exact, integer pipe
    }
    double y4 = m * r;                       // RN(m*r): within ~2^-51 of sqrt(m)

    // ---------------- last two Newton iterations, bit-exact -----------------
    // q0 = RN(m*r) == y4 for both divisions (r unchanged), so each CR quotient
    // needs a single Markstein correction: eps_pre ~ 2^-50 * 2^-51 -> CR.
    double q1 = __fma_rn(__fma_rn(-y4, y4, m), r, y4);   // RN(m / y4)
    double y5 = halve(y4 + q1);                           // reference i=4 image
    double q2 = __fma_rn(__fma_rn(-y5, y4, m), r, y4);   // RN(m / y5)
    double y6 = halve(y5 + q2);                           // == y12 (even tail)

    // Re-apply exponent: 2^kk = integer add on the exponent field (exact,
    // including the carry when y == 2.0).
    uint64_t rbits = double_as_u64(y6) + ((uint64_t)kk << 52);

    // ---------------- special-case muxes (same order as reference) ---------
    const uint64_t s_bit  = u >> 63;
    const bool m_any      = (u & MANT_MASK) != 0ULL;
    const bool e_all_one  = (e_x == 0x7FF);
    const bool e_is_zero  = (e_x == 0);
    if (s_bit)                              rbits = NAN_BITS;
    if (e_all_one &&  m_any)                rbits = NAN_BITS;
    if (e_all_one && !m_any && s_bit == 0)  rbits = INF_BITS;
    if (e_is_zero && !m_any)                rbits = 0ULL;

    // ---------------- unpack: shuffle + float4 stores, fully coalesced ------
    // Warp output = contiguous 2048 floats. Lane writes the float4 at
    // q0 = j*128 + 4*lane; its 4 bits share word k = 4j+(lane>>3), source
    // lane k>>1 = 2j+(lane>>4), parity k&1 = (lane>>3)&1.
    const unsigned rhi = (unsigned)(rbits >> 32);
    const unsigned rlo = (unsigned)rbits;
    float4* otile4 = (float4*)(out + (size_t)warpRow0 * 64);
    const int src    = lane >> 4;            // added to 2j
    const int parity = (lane >> 3) & 1;      // rhi vs rlo
    const int sh     = 28 - 4 * (lane & 7);  // bottom bit of my 4-bit group
    #pragma unroll
    for (int j = 0; j < 16; j++) {
        unsigned whi = __shfl_sync(0xffffffffu, rhi, 2 * j + src);
        unsigned wlo = __shfl_sync(0xffffffffu, rlo, 2 * j + src);
        unsigned w   = parity ? wlo : whi;
        unsigned b   = w >> sh;              // my 4 bits in b[3..0], MSB first
        float4 v;
        v.x = (float)((b >> 3) & 1u);
        v.y = (float)((b >> 2) & 1u);
        v.z = (float)((b >> 1) & 1u);
        v.w = (float)(b & 1u);
        otile4[j * 32 + lane] = v;
    }
}

extern "C" void kernel_launch(void* const* d_in, const int* in_sizes, int n_in,
                              void* d_out, int out_size)
{
    const float* x = (const float*)d_in[0];
    float* out = (float*)d_out;
    const int n = in_sizes[0] / 64;
    const int threads = 256;
    const int blocks = (n + threads - 1) / threads;
    spike_sqrt_kernel<<<blocks, threads>>>(x, out, n);
}

// round 11
// speedup vs baseline: 1.0577x; 1.0067x over previous
#include <cuda_runtime.h>
#include <cstdint>

static __device__ __forceinline__ double u64_as_double(uint64_t u) {
    return __longlong_as_double((long long)u);
}
static __device__ __forceinline__ uint64_t double_as_u64(double d) {
    return (uint64_t)__double_as_longlong(d);
}
static __device__ __forceinline__ double rsqrt_approx(double v) {
    double r;
    asm("rsqrt.approx.ftz.f64 %0, %1;" : "=d"(r) : "d"(v));
    return r;
}
// Exact multiply by 0.5 for a normal double (exponent decrement, ALU pipe).
static __device__ __forceinline__ double halve(double s) {
    return __hiloint2double(__double2hiint(s) - 0x00100000, __double2loint(s));
}

#define SQRT2_MANT 1865452045155277ULL
#define NAN_BITS   0x7FF8000000000000ULL
#define INF_BITS   0x7FF0000000000000ULL
#define MANT_MASK  0xFFFFFFFFFFFFFULL
#define FONE       0x3F800000u

__global__ void __launch_bounds__(256)
spike_sqrt_kernel(const float* __restrict__ x, float* __restrict__ out, int n)
{
    const int tid  = blockIdx.x * blockDim.x + threadIdx.x;
    const int lane = threadIdx.x & 31;
    const int warpRow0 = (tid >> 5) << 5;       // first row of this warp's 32-row tile
    if (warpRow0 >= n) return;

    // ---------------- pack: float4 loads + FFMA nibbles + butterfly OR ------
    // Warp tile = 2048 contiguous floats. Lane l, iter j loads the float4 at
    // flat j*128 + 4l -> word k = 4j + (l>>3), bits [31-4*(l&7) .. 28-4*(l&7)]
    // (MSB-first). Pulses are exactly 0.0f/1.0f, so the nibble is an exact
    // small-int FFMA chain (fp32 pipe, otherwise idle). OR-reduce each 8-lane
    // group (the lanes sharing a word) via shfl_xor butterfly; lanes 2j and
    // 2j+1 capture words 4j+{0,1} and 4j+{2,3} = their (hi, lo).
    const float4* tile4 = (const float4*)(x + (size_t)warpRow0 * 64);
    const int nsh = 28 - 4 * (lane & 7);
    unsigned hi = 0, lo = 0;
    #pragma unroll
    for (int j = 0; j < 16; j++) {
        float4 p = __ldcs(&tile4[j * 32 + lane]);
        float nf = fmaf(p.x, 8.0f, fmaf(p.y, 4.0f, fmaf(p.z, 2.0f, p.w)));
        unsigned v = ((unsigned)(int)nf) << nsh;
        v |= __shfl_xor_sync(0xffffffffu, v, 1);
        v |= __shfl_xor_sync(0xffffffffu, v, 2);
        v |= __shfl_xor_sync(0xffffffffu, v, 4);
        // group s now all hold word 4j+s
        unsigned hi_c = __shfl_sync(0xffffffffu, v, (lane & 1) << 4);        // s = 2*(l&1)
        unsigned lo_c = __shfl_sync(0xffffffffu, v, ((lane & 1) << 4) + 8);  // s = 2*(l&1)+1
        if ((lane >> 1) == j) { hi = hi_c; lo = lo_c; }
    }
    const uint64_t u = ((uint64_t)hi << 32) | lo;

    // ---------------- normalized frame: f = 2^(2k) * m,  m in [1,4) ---------
    const long long e_x    = (long long)((u >> 52) & 0x7FFULL);
    const long long e_real = e_x - 1023;
    const long long oddb   = (e_real & 1);
    const long long kk     = (e_real >> 1);                 // arithmetic shift
    const double m = u64_as_double((u & MANT_MASK) | ((uint64_t)(1023 + oddb) << 52));

    // ---------------- rsqrt sprint to the y4 region -------------------------
    // Any point within ~2^-43 of sqrt(m) yields bit-identical y5, y6 (Newton
    // contraction: pre-round images differ by ~e^2 <= 2^-86). rsqrt NR:
    // delta -> 1.5*delta^2; 3 steps floor at ~2^-51.5 from the MUFU seed.
    double r = rsqrt_approx(m);
    #pragma unroll
    for (int i = 0; i < 3; i++) {
        double t = m * r;
        double e = __fma_rn(-t, r, 1.0);
        r = __fma_rn(halve(r), e, r);       // halve(r): exact, integer pipe
    }
    double y4 = m * r;                       // RN(m*r): within ~2^-51 of sqrt(m)

    // ---------------- last two Newton iterations, bit-exact -----------------
    // q0 = RN(m*r) == y4 for both divisions, so each CR quotient is a single
    // Markstein correction (eps_pre ~ 2^-101 -> CR).
    double q1 = __fma_rn(__fma_rn(-y4, y4, m), r, y4);   // RN(m / y4)
    double y5 = halve(y4 + q1);                           // reference i=4 image
    double q2 = __fma_rn(__fma_rn(-y5, y4, m), r, y4);   // RN(m / y5)
    double y6 = halve(y5 + q2);                           // == y12 (even tail)

    // Re-apply exponent: 2^kk = integer add on the exponent field (exact,
    // including the carry when y == 2.0).
    uint64_t rbits = double_as_u64(y6) + ((uint64_t)kk << 52);

    // ---------------- special-case muxes (same order as reference) ---------
    const uint64_t s_bit  = u >> 63;
    const bool m_any      = (u & MANT_MASK) != 0ULL;
    const bool e_all_one  = (e_x == 0x7FF);
    const bool e_is_zero  = (e_x == 0);
    if (s_bit)                              rbits = NAN_BITS;
    if (e_all_one &&  m_any)                rbits = NAN_BITS;
    if (e_all_one && !m_any && s_bit == 0)  rbits = INF_BITS;
    if (e_is_zero && !m_any)                rbits = 0ULL;

    // ---------------- unpack: shuffle + uint4 stores, fully coalesced -------
    // Lane writes the 4 floats at flat j*128 + 4*lane; bits live in word
    // k = 4j+(lane>>3) (source lane k>>1 = 2j+(lane>>4), parity (lane>>3)&1)
    // at offset 28-4*(lane&7).
    const unsigned rhi = (unsigned)(rbits >> 32);
    const unsigned rlo = (unsigned)rbits;
    uint4* otile4 = (uint4*)(out + (size_t)warpRow0 * 64);
    const int src    = lane >> 4;
    const int parity = (lane >> 3) & 1;
    const int sh     = nsh;                  // same 28 - 4*(lane&7)
    #pragma unroll
    for (int j = 0; j < 16; j++) {
        unsigned whi = __shfl_sync(0xffffffffu, rhi, 2 * j + src);
        unsigned wlo = __shfl_sync(0xffffffffu, rlo, 2 * j + src);
        unsigned w   = parity ? wlo : whi;
        unsigned b   = w >> sh;              // my 4 bits in b[3..0], MSB first
        uint4 v;
        v.x = ((b >> 3) & 1u) * FONE;
        v.y = ((b >> 2) & 1u) * FONE;
        v.z = ((b >> 1) & 1u) * FONE;
        v.w = (b & 1u) * FONE;
        __stcs(&otile4[j * 32 + lane], v);
    }
}

extern "C" void kernel_launch(void* const* d_in, const int* in_sizes, int n_in,
                              void* d_out, int out_size)
{
    const float* x = (const float*)d_in[0];
    float* out = (float*)d_out;
    const int n = in_sizes[0] / 64;
    const int threads = 256;
    const int blocks = (n + threads - 1) / threads;
    spike_sqrt_kernel<<<blocks, threads>>>(x, out, n);
}

// round 13
// speedup vs baseline: 1.0701x; 1.0117x over previous
#include <cuda_runtime.h>
#include <cstdint>

static __device__ __forceinline__ double u64_as_double(uint64_t u) {
    return __longlong_as_double((long long)u);
}
static __device__ __forceinline__ uint64_t double_as_u64(double d) {
    return (uint64_t)__double_as_longlong(d);
}
static __device__ __forceinline__ double rsqrt_approx(double v) {
    double r;
    asm("rsqrt.approx.ftz.f64 %0, %1;" : "=d"(r) : "d"(v));
    return r;
}
// Exact multiply by 0.5 for a normal double (exponent decrement, ALU pipe).
static __device__ __forceinline__ double halve(double s) {
    return __hiloint2double(__double2hiint(s) - 0x00100000, __double2loint(s));
}

#define SQRT2_MANT 1865452045155277ULL
#define NAN_BITS   0x7FF8000000000000ULL
#define INF_BITS   0x7FF0000000000000ULL
#define MANT_MASK  0xFFFFFFFFFFFFFULL
#define FONE       0x3F800000u

__global__ void __launch_bounds__(256, 8)
spike_sqrt_kernel(const float* __restrict__ x, float* __restrict__ out, int n)
{
    const int tid  = blockIdx.x * blockDim.x + threadIdx.x;
    const int lane = threadIdx.x & 31;
    const int warpRow0 = (tid >> 5) << 5;       // first row of this warp's 32-row tile
    if (warpRow0 >= n) return;

    // ---------------- pack: ballot transpose, fully coalesced ----------------
    // (R10-proven form: 32 regs, 84% occ.) Iter k loads 32 consecutive floats
    // = half of row k>>1; ballot gives those 32 bits; streaming hint since
    // each line is read exactly once.
    const float* tile = x + (size_t)warpRow0 * 64;
    unsigned hi = 0, lo = 0;
    #pragma unroll
    for (int k = 0; k < 64; k++) {
        float v = __ldcs(tile + k * 32 + lane);
        unsigned mask = __ballot_sync(0xffffffffu, v > 0.5f);
        unsigned w = __brev(mask);
        if ((k >> 1) == lane) { if (k & 1) lo = w; else hi = w; }
    }
    const uint64_t u = ((uint64_t)hi << 32) | lo;

    // ---------------- normalized frame: f = 2^(2k) * m,  m in [1,4) ---------
    const long long e_x    = (long long)((u >> 52) & 0x7FFULL);
    const long long e_real = e_x - 1023;
    const long long oddb   = (e_real & 1);
    const long long kk     = (e_real >> 1);                 // arithmetic shift
    const double m = u64_as_double((u & MANT_MASK) | ((uint64_t)(1023 + oddb) << 52));

    // ---------------- rsqrt sprint to the y4 region -------------------------
    // Any point within ~2^-43 of sqrt(m) yields bit-identical y5, y6 (Newton
    // contraction: pre-round images differ by ~e^2 <= 2^-86). rsqrt NR:
    // delta -> 1.5*delta^2; 3 steps floor at ~2^-51.5 from the MUFU seed.
    double r = rsqrt_approx(m);
    #pragma unroll
    for (int i = 0; i < 3; i++) {
        double t = m * r;
        double e = __fma_rn(-t, r, 1.0);
        r = __fma_rn(halve(r), e, r);       // halve(r): exact, integer pipe
    }
    double y4 = m * r;                       // RN(m*r): within ~2^-51 of sqrt(m)

    // ---------------- last two Newton iterations, bit-exact -----------------
    // q0 = RN(m*r) == y4 for both divisions, so each CR quotient is a single
    // Markstein correction (eps_pre ~ 2^-101 -> CR).
    double q1 = __fma_rn(__fma_rn(-y4, y4, m), r, y4);   // RN(m / y4)
    double y5 = halve(y4 + q1);                           // reference i=4 image
    double q2 = __fma_rn(__fma_rn(-y5, y4, m), r, y4);   // RN(m / y5)
    double y6 = halve(y5 + q2);                           // == y12 (even tail)

    // Re-apply exponent: 2^kk = integer add on the exponent field (exact,
    // including the carry when y == 2.0).
    uint64_t rbits = double_as_u64(y6) + ((uint64_t)kk << 52);

    // ---------------- special-case muxes (same order as reference) ---------
    const uint64_t s_bit  = u >> 63;
    const bool m_any      = (u & MANT_MASK) != 0ULL;
    const bool e_all_one  = (e_x == 0x7FF);
    const bool e_is_zero  = (e_x == 0);
    if (s_bit)                              rbits = NAN_BITS;
    if (e_all_one &&  m_any)                rbits = NAN_BITS;
    if (e_all_one && !m_any && s_bit == 0)  rbits = INF_BITS;
    if (e_is_zero && !m_any)                rbits = 0ULL;

    // ---------------- unpack: shuffle + uint4 stores, fully coalesced -------
    // Lane writes the 4 floats at flat j*128 + 4*lane; bits live in word
    // k = 4j+(lane>>3) (source lane k>>1 = 2j+(lane>>4), parity (lane>>3)&1)
    // at offset 28-4*(lane&7). Integer select (bit * 0x3F800000) avoids the
    // conversion pipe entirely; streaming store (write-once data).
    const unsigned rhi = (unsigned)(rbits >> 32);
    const unsigned rlo = (unsigned)rbits;
    uint4* otile4 = (uint4*)(out + (size_t)warpRow0 * 64);
    const int src    = lane >> 4;
    const int parity = (lane >> 3) & 1;
    const int sh     = 28 - 4 * (lane & 7);
    #pragma unroll
    for (int j = 0; j < 16; j++) {
        unsigned whi = __shfl_sync(0xffffffffu, rhi, 2 * j + src);
        unsigned wlo = __shfl_sync(0xffffffffu, rlo, 2 * j + src);
        unsigned w   = parity ? wlo : whi;
        unsigned b   = w >> sh;              // my 4 bits in b[3..0], MSB first
        uint4 v;
        v.x = ((b >> 3) & 1u) * FONE;
        v.y = ((b >> 2) & 1u) * FONE;
        v.z = ((b >> 1) & 1u) * FONE;
        v.w = (b & 1u) * FONE;
        __stcs(&otile4[j * 32 + lane], v);
    }
}

extern "C" void kernel_launch(void* const* d_in, const int* in_sizes, int n_in,
                              void* d_out, int out_size)
{
    const float* x = (const float*)d_in[0];
    float* out = (float*)d_out;
    const int n = in_sizes[0] / 64;
    const int threads = 256;
    const int blocks = (n + threads - 1) / threads;
    spike_sqrt_kernel<<<blocks, threads>>>(x, out, n);
}